// round 4
// baseline (speedup 1.0000x reference)
#include <cuda_runtime.h>
#include <cstdint>

// out[n,w,i] = (1/m) * sum_u x[n,u,i] * weight[n,u] * W[u,w]
// Irreps: 256x0e + 128x1o + 64x2e + 32x3o ; DIM=1184, WNUM=480

#define DIM_ 1184
#define WNUM_ 480
typedef unsigned long long ull;

__device__ __forceinline__ void cp_async16(uint32_t dst, const void* src) {
    asm volatile("cp.async.cg.shared.global [%0], [%1], 16;" :: "r"(dst), "l"(src));
}
__device__ __forceinline__ void cp_commit() { asm volatile("cp.async.commit_group;"); }
__device__ __forceinline__ void cp_wait0()  { asm volatile("cp.async.wait_group 0;" ::: "memory"); }

// D: irrep dim (2l+1), DP: padded D for LDS.128 frags, M: multiplicity,
// BN x BW: row x out-channel tile, BK: k-tile, TN x TW: per-thread tile, NT: threads
template<int D, int DP, int M, int BN, int BW, int BK, int TN, int TW, int NT>
__global__ __launch_bounds__(NT)
void tp3_kernel(const float* __restrict__ x, const float* __restrict__ wt,
                const float* __restrict__ Wm, float* __restrict__ out,
                int nrows, int xo, int wo)
{
    constexpr int THW = BW / TW;
    constexpr int THN = BN / TN;
    static_assert(THW * THN == NT, "thread grid");
    constexpr int RT  = NT / BN;        // fill threads per row
    constexpr int KPT = BK / RT;        // wt floats per fill thread
    constexpr int CPT = KPT * D;        // x floats per fill thread (contiguous)
    constexpr int AFP = TN * DP;        // A-frag floats (padded)
    constexpr int ROWLEN = BN * DP + 4; // padded row (stagger banks)
    static_assert(ROWLEN % 4 == 0, "row align");
    static_assert(AFP % 4 == 0, "A frag vec4");
    static_assert((TN * DP) % 4 == 0, "frag base align");
    constexpr int TILES = M / BK;
    constexpr int NB4 = BK * BW / 4;
    static_assert(CPT % 2 == 0, "x vec2");

    __shared__ float As[2][BK][ROWLEN];
    __shared__ float Bs[2][BK][BW];

    const int tid = threadIdx.x;
    const int twi = tid % THW;
    const int tni = tid / THW;
    const int n0  = blockIdx.x * BN;
    const int rf  = tid / RT;
    const int q   = tid % RT;
    const bool rvalid = (n0 + rf) < nrows;
    const float inv_m = 1.0f / (float)M;

    const float* xrow = x  + (size_t)(n0 + rf) * DIM_  + xo + q * CPT;
    const float* wrow = wt + (size_t)(n0 + rf) * WNUM_ + wo + q * KPT;
    const uint32_t bs0 = (uint32_t)__cvta_generic_to_shared(&Bs[0][0][0]);

    ull acc[TN * D][TW / 2];
#pragma unroll
    for (int e = 0; e < TN * D; ++e)
#pragma unroll
        for (int j2 = 0; j2 < TW / 2; ++j2) acc[e][j2] = 0ull;

    alignas(16) float xr[CPT];
    alignas(16) float wr[KPT];

    auto ld_regs = [&](int u0) {
        if (rvalid) {
            const float* xp = xrow + (size_t)u0 * D;
            if constexpr (CPT % 4 == 0) {
#pragma unroll
                for (int v = 0; v < CPT / 4; ++v)
                    reinterpret_cast<float4*>(xr)[v] =
                        reinterpret_cast<const float4*>(xp)[v];
            } else {
#pragma unroll
                for (int v = 0; v < CPT / 2; ++v)
                    reinterpret_cast<float2*>(xr)[v] =
                        reinterpret_cast<const float2*>(xp)[v];
            }
            const float* wp = wrow + u0;
            if constexpr (KPT % 4 == 0) {
#pragma unroll
                for (int v = 0; v < KPT / 4; ++v)
                    reinterpret_cast<float4*>(wr)[v] =
                        reinterpret_cast<const float4*>(wp)[v];
            } else if constexpr (KPT % 2 == 0) {
#pragma unroll
                for (int v = 0; v < KPT / 2; ++v)
                    reinterpret_cast<float2*>(wr)[v] =
                        reinterpret_cast<const float2*>(wp)[v];
            } else {
#pragma unroll
                for (int v = 0; v < KPT; ++v) wr[v] = wp[v];
            }
        } else {
#pragma unroll
            for (int j = 0; j < CPT; ++j) xr[j] = 0.0f;
#pragma unroll
            for (int j = 0; j < KPT; ++j) wr[j] = 0.0f;
        }
    };

    auto ld_bs = [&](int u0, int buf) {
        const float4* src = reinterpret_cast<const float4*>(Wm + (size_t)u0 * BW);
        uint32_t dst = bs0 + (uint32_t)buf * (BK * BW * 4);
#pragma unroll
        for (int v = 0; v < (NB4 + NT - 1) / NT; ++v) {
            int idx = tid + v * NT;
            if ((NB4 % NT == 0) || idx < NB4)
                cp_async16(dst + idx * 16, src + idx);
        }
    };

    auto st_as = [&](int buf) {
#pragma unroll
        for (int j = 0; j < CPT; ++j) {
            int kk = q * KPT + j / D;
            int ii = j % D;
            As[buf][kk][rf * DP + ii] = xr[j] * (wr[j / D] * inv_m);
        }
    };

    auto compute = [&](int buf) {
#pragma unroll
        for (int k = 0; k < BK; ++k) {
            alignas(16) float af[AFP];
            const float* ap = &As[buf][k][tni * TN * DP];
#pragma unroll
            for (int v = 0; v < AFP / 4; ++v)
                reinterpret_cast<float4*>(af)[v] =
                    reinterpret_cast<const float4*>(ap)[v];

            ull bf[TW / 2];
            const ull* bp = reinterpret_cast<const ull*>(&Bs[buf][k][0]);
#pragma unroll
            for (int j2 = 0; j2 < TW / 2; ++j2) bf[j2] = bp[twi + j2 * THW];

#pragma unroll
            for (int a = 0; a < TN; ++a) {
#pragma unroll
                for (int i = 0; i < D; ++i) {
                    ull a2;
                    asm("mov.b64 %0, {%1, %1};"
                        : "=l"(a2) : "r"(__float_as_uint(af[a * DP + i])));
#pragma unroll
                    for (int j2 = 0; j2 < TW / 2; ++j2)
                        asm("fma.rn.f32x2 %0, %1, %2, %0;"
                            : "+l"(acc[a * D + i][j2]) : "l"(a2), "l"(bf[j2]));
                }
            }
        }
    };

    // prologue: tile 0
    ld_regs(0);
    ld_bs(0, 0);
    cp_commit();
    st_as(0);
    cp_wait0();
    __syncthreads();

#pragma unroll 1
    for (int t = 0; t < TILES; ++t) {
        const int cur = t & 1;
        if (t + 1 < TILES) {
            ld_regs((t + 1) * BK);
            ld_bs((t + 1) * BK, cur ^ 1);
            cp_commit();
        }
        compute(cur);
        if (t + 1 < TILES) {
            st_as(cur ^ 1);
            cp_wait0();
        }
        __syncthreads();
    }

    // epilogue: w pair (wlo, wlo+1), wlo = twi*2 + j2*2*THW
#pragma unroll
    for (int a = 0; a < TN; ++a) {
        int gn = n0 + tni * TN + a;
        if (gn >= nrows) continue;
        float* orow = out + (size_t)gn * DIM_ + xo;
#pragma unroll
        for (int j2 = 0; j2 < TW / 2; ++j2) {
            int wlo = twi * 2 + j2 * 2 * THW;
#pragma unroll
            for (int i = 0; i < D; ++i) {
                ull v = acc[a * D + i][j2];
                float lo = __uint_as_float((uint32_t)(v & 0xffffffffull));
                float hi = __uint_as_float((uint32_t)(v >> 32));
                if constexpr (D == 1) {
                    *reinterpret_cast<float2*>(orow + wlo) = make_float2(lo, hi);
                } else {
                    orow[(size_t)wlo * D + i]       = lo;
                    orow[(size_t)(wlo + 1) * D + i] = hi;
                }
            }
        }
    }
}

extern "C" void kernel_launch(void* const* d_in, const int* in_sizes, int n_in,
                              void* d_out, int out_size)
{
    const float* x  = (const float*)d_in[0];
    const float* wtp = (const float*)d_in[1];
    const float* W0 = (const float*)d_in[2];
    const float* W1 = (const float*)d_in[3];
    const float* W2 = (const float*)d_in[4];
    const float* W3 = (const float*)d_in[5];
    float* out = (float*)d_out;

    const int nrows = in_sizes[0] / DIM_;

    // b0: m=256,d=1  128x256 tile, 512 thr, TN=8 TW=8 (acc 64)
    tp3_kernel<1, 1, 256, 128, 256, 16, 8, 8, 512>
        <<<(nrows + 127) / 128, 512>>>(x, wtp, W0, out, nrows, 0, 0);
    // b1: m=128,d=3 (DP=4)  64x128 tile, TN=4 TW=8 (acc 96)
    tp3_kernel<3, 4, 128, 64, 128, 8, 4, 8, 256>
        <<<(nrows + 63) / 64, 256>>>(x, wtp, W1, out, nrows, 256, 256);
    // b2: m=64,d=5 (DP=6)   64x64 tile, TN=2 TW=8 (acc 80)
    tp3_kernel<5, 6, 64, 64, 64, 8, 2, 8, 256>
        <<<(nrows + 63) / 64, 256>>>(x, wtp, W2, out, nrows, 640, 384);
    // b3: m=32,d=7 (DP=8)   64x32 tile, TN=2 TW=4 (acc 56)
    tp3_kernel<7, 8, 32, 64, 32, 8, 2, 4, 256>
        <<<(nrows + 63) / 64, 256>>>(x, wtp, W3, out, nrows, 960, 448);
}

// round 5
// speedup vs baseline: 1.1273x; 1.1273x over previous
#include <cuda_runtime.h>
#include <cstdint>

// out[n,w,i] = (1/m) * sum_u x[n,u,i] * weight[n,u] * W[u,w]
// Irreps: 256x0e + 128x1o + 64x2e + 32x3o ; DIM=1184, WNUM=480
// Fused single-launch dispatch: all 4 irrep blocks co-resident.

#define DIM_ 1184
#define WNUM_ 480
typedef unsigned long long ull;

__device__ __forceinline__ void cp_async16(uint32_t dst, const void* src) {
    asm volatile("cp.async.cg.shared.global [%0], [%1], 16;" :: "r"(dst), "l"(src));
}
__device__ __forceinline__ void cp_commit() { asm volatile("cp.async.commit_group;"); }
__device__ __forceinline__ void cp_wait0()  { asm volatile("cp.async.wait_group 0;" ::: "memory"); }

#define SMEM_BYTES 37504

// One irrep block GEMM tile. NT=256 threads.
// D: irrep dim, DP: padded D (LDS.128 frags), M: multiplicity,
// BN x BW tile (BW == M, full width), BK: k-tile, TN x TW per-thread.
template<int D, int DP, int M, int BN, int BW, int BK, int TN, int TW>
__device__ __forceinline__
void run_tp(char* smraw,
            const float* __restrict__ x, const float* __restrict__ wt,
            const float* __restrict__ Wm, float* __restrict__ out,
            int n0, int nrows, int xo, int wo)
{
    constexpr int NT  = 256;
    constexpr int THW = BW / TW;
    constexpr int THN = BN / TN;
    static_assert(THW * THN == NT, "grid");
    constexpr int RT  = NT / BN;         // fill threads per row
    constexpr int KPT = BK / RT;         // wt floats per fill thread
    constexpr int CPT = KPT * D;         // x floats per fill thread
    constexpr int AFP = TN * DP;
    constexpr int ROWLEN = BN * DP + 4;  // floats, %4==0
    static_assert(ROWLEN % 4 == 0, "rowpad");
    static_assert(AFP % 4 == 0, "afrag");
    constexpr int TILES = M / BK;
    constexpr int NB4 = BK * BW / 4;
    constexpr int AS_BYTES = 2 * BK * ROWLEN * 4;
    static_assert(AS_BYTES + 2 * BK * BW * 4 <= SMEM_BYTES, "smem");

    float (*As)[BK][ROWLEN] = reinterpret_cast<float (*)[BK][ROWLEN]>(smraw);
    float (*Bs)[BK][BW]     = reinterpret_cast<float (*)[BK][BW]>(smraw + AS_BYTES);

    const int tid = threadIdx.x;
    const int twi = tid % THW;
    const int tni = tid / THW;
    const int rf  = tid / RT;
    const int q   = tid % RT;
    const bool rvalid = (n0 + rf) < nrows;
    const float inv_m = 1.0f / (float)M;

    const float* xrow = x  + (size_t)(n0 + rf) * DIM_  + xo + q * CPT;
    const float* wrow = wt + (size_t)(n0 + rf) * WNUM_ + wo + q * KPT;
    const uint32_t bs0 = (uint32_t)__cvta_generic_to_shared(&Bs[0][0][0]);

    ull acc[TN * D][TW / 2];
#pragma unroll
    for (int e = 0; e < TN * D; ++e)
#pragma unroll
        for (int j2 = 0; j2 < TW / 2; ++j2) acc[e][j2] = 0ull;

    alignas(8) float xr[CPT];
    alignas(8) float wr[KPT];

    auto ld_regs = [&](int u0) {
        if (rvalid) {
            const float* xp = xrow + (size_t)u0 * D;
            if constexpr (CPT % 2 == 0) {
#pragma unroll
                for (int v = 0; v < CPT / 2; ++v)
                    reinterpret_cast<float2*>(xr)[v] =
                        reinterpret_cast<const float2*>(xp)[v];
            } else {
#pragma unroll
                for (int v = 0; v < CPT; ++v) xr[v] = xp[v];
            }
            const float* wp = wrow + u0;
            if constexpr (KPT % 2 == 0) {
#pragma unroll
                for (int v = 0; v < KPT / 2; ++v)
                    reinterpret_cast<float2*>(wr)[v] =
                        reinterpret_cast<const float2*>(wp)[v];
            } else {
#pragma unroll
                for (int v = 0; v < KPT; ++v) wr[v] = wp[v];
            }
        } else {
#pragma unroll
            for (int j = 0; j < CPT; ++j) xr[j] = 0.0f;
#pragma unroll
            for (int j = 0; j < KPT; ++j) wr[j] = 0.0f;
        }
    };

    auto ld_bs = [&](int u0, int buf) {
        const float4* src = reinterpret_cast<const float4*>(Wm + (size_t)u0 * M);
        uint32_t dst = bs0 + (uint32_t)buf * (BK * BW * 4);
#pragma unroll
        for (int v = 0; v < (NB4 + NT - 1) / NT; ++v) {
            int idx = tid + v * NT;
            if ((NB4 % NT == 0) || idx < NB4)
                cp_async16(dst + idx * 16, src + idx);
        }
    };

    auto st_as = [&](int buf) {
#pragma unroll
        for (int j = 0; j < CPT; ++j) {
            int kk = q * KPT + j / D;
            int ii = j % D;
            As[buf][kk][rf * DP + ii] = xr[j] * (wr[j / D] * inv_m);
        }
    };

    auto compute = [&](int buf) {
#pragma unroll
        for (int k = 0; k < BK; ++k) {
            alignas(16) float af[AFP];
            const float* ap = &As[buf][k][tni * TN * DP];
#pragma unroll
            for (int v = 0; v < AFP / 4; ++v)
                reinterpret_cast<float4*>(af)[v] =
                    reinterpret_cast<const float4*>(ap)[v];

            ull bf[TW / 2];
            const ull* bp = reinterpret_cast<const ull*>(&Bs[buf][k][0]);
#pragma unroll
            for (int j2 = 0; j2 < TW / 2; ++j2) bf[j2] = bp[twi + j2 * THW];

#pragma unroll
            for (int a = 0; a < TN; ++a)
#pragma unroll
                for (int i = 0; i < D; ++i) {
                    ull a2;
                    asm("mov.b64 %0, {%1, %1};"
                        : "=l"(a2) : "r"(__float_as_uint(af[a * DP + i])));
#pragma unroll
                    for (int j2 = 0; j2 < TW / 2; ++j2)
                        asm("fma.rn.f32x2 %0, %1, %2, %0;"
                            : "+l"(acc[a * D + i][j2]) : "l"(a2), "l"(bf[j2]));
                }
        }
    };

    ld_regs(0);
    ld_bs(0, 0);
    cp_commit();
    st_as(0);
    cp_wait0();
    __syncthreads();

#pragma unroll 1
    for (int t = 0; t < TILES; ++t) {
        const int cur = t & 1;
        if (t + 1 < TILES) {
            ld_regs((t + 1) * BK);
            ld_bs((t + 1) * BK, cur ^ 1);
            cp_commit();
        }
        compute(cur);
        if (t + 1 < TILES) {
            st_as(cur ^ 1);
            cp_wait0();
        }
        __syncthreads();
    }

    // epilogue: w-pair (wlo, wlo+1), wlo = twi*2 + j2*2*THW
    // each (a, j2) writes a contiguous 2*D-float span
#pragma unroll
    for (int a = 0; a < TN; ++a) {
        int gn = n0 + tni * TN + a;
        if (gn >= nrows) continue;
        float* orow = out + (size_t)gn * DIM_ + xo;
#pragma unroll
        for (int j2 = 0; j2 < TW / 2; ++j2) {
            int wlo = twi * 2 + j2 * 2 * THW;
#pragma unroll
            for (int i = 0; i < D; ++i) {
                ull v = acc[a * D + i][j2];
                float lo = __uint_as_float((uint32_t)(v & 0xffffffffull));
                float hi = __uint_as_float((uint32_t)(v >> 32));
                if constexpr (D == 1) {
                    *reinterpret_cast<float2*>(orow + wlo) = make_float2(lo, hi);
                } else {
                    orow[(size_t)wlo * D + i]       = lo;
                    orow[(size_t)(wlo + 1) * D + i] = hi;
                }
            }
        }
    }
}

// chunk pattern of 5 blocks: {b0(32 rows), b1(16), b1(16), b2(32), b3(32)}
// covers 32 rows of every irrep block per chunk. 100000 = 32*3125.
#define NCHUNK 3125

__global__ __launch_bounds__(256)
void tp_fused_kernel(const float* __restrict__ x, const float* __restrict__ wt,
                     const float* __restrict__ W0, const float* __restrict__ W1,
                     const float* __restrict__ W2, const float* __restrict__ W3,
                     float* __restrict__ out, int nrows)
{
    __shared__ alignas(16) char smraw[SMEM_BYTES];
    const int bid = blockIdx.x;
    const int r = bid / 5;
    const int t = bid - r * 5;

    if (t == 0) {
        // b0: m=256, d=1 | BN=32, BW=256, BK=16, TN=4, TW=8 (acc 32f)
        run_tp<1, 1, 256, 32, 256, 16, 4, 8>(smraw, x, wt, W0, out,
                                             r * 32, nrows, 0, 0);
    } else if (t <= 2) {
        // b1: m=128, d=3 (DP=4) | BN=16, BW=128, BK=16, TN=2, TW=4 (acc 24f)
        run_tp<3, 4, 128, 16, 128, 16, 2, 4>(smraw, x, wt, W1, out,
                                             (2 * r + (t - 1)) * 16, nrows, 256, 256);
    } else if (t == 3) {
        // b2: m=64, d=5 (DP=6) | BN=32, BW=64, BK=16, TN=2, TW=4 (acc 40f)
        run_tp<5, 6, 64, 32, 64, 16, 2, 4>(smraw, x, wt, W2, out,
                                           r * 32, nrows, 640, 384);
    } else {
        // b3: m=32, d=7 (DP=8) | BN=32, BW=32, BK=16, TN=2, TW=2 (acc 28f)
        run_tp<7, 8, 32, 32, 32, 16, 2, 2>(smraw, x, wt, W3, out,
                                           r * 32, nrows, 960, 448);
    }
}

extern "C" void kernel_launch(void* const* d_in, const int* in_sizes, int n_in,
                              void* d_out, int out_size)
{
    const float* x  = (const float*)d_in[0];
    const float* wtp = (const float*)d_in[1];
    const float* W0 = (const float*)d_in[2];
    const float* W1 = (const float*)d_in[3];
    const float* W2 = (const float*)d_in[4];
    const float* W3 = (const float*)d_in[5];
    float* out = (float*)d_out;

    const int nrows = in_sizes[0] / DIM_;
    const int nchunk = (nrows + 31) / 32;          // rows per chunk: 32
    tp_fused_kernel<<<nchunk * 5, 256>>>(x, wtp, W0, W1, W2, W3, out, nrows);
}

// round 6
// speedup vs baseline: 1.1456x; 1.0162x over previous
#include <cuda_runtime.h>
#include <cstdint>

// out[n,w,i] = (1/m) * sum_u x[n,u,i] * weight[n,u] * W[u,w]
// Irreps: 256x0e + 128x1o + 64x2e + 32x3o ; DIM=1184, WNUM=480
// Fused single-launch dispatch: all 4 irrep blocks co-resident.
// R6: __launch_bounds__(256,3) -> <=84 regs -> 3 CTAs/SM (was 2 at 86 regs).

#define DIM_ 1184
#define WNUM_ 480
typedef unsigned long long ull;

__device__ __forceinline__ void cp_async16(uint32_t dst, const void* src) {
    asm volatile("cp.async.cg.shared.global [%0], [%1], 16;" :: "r"(dst), "l"(src));
}
__device__ __forceinline__ void cp_commit() { asm volatile("cp.async.commit_group;"); }
__device__ __forceinline__ void cp_wait0()  { asm volatile("cp.async.wait_group 0;" ::: "memory"); }

#define SMEM_BYTES 37504

template<int D, int DP, int M, int BN, int BW, int BK, int TN, int TW>
__device__ __forceinline__
void run_tp(char* smraw,
            const float* __restrict__ x, const float* __restrict__ wt,
            const float* __restrict__ Wm, float* __restrict__ out,
            int n0, int nrows, int xo, int wo)
{
    constexpr int NT  = 256;
    constexpr int THW = BW / TW;
    constexpr int THN = BN / TN;
    static_assert(THW * THN == NT, "grid");
    constexpr int RT  = NT / BN;         // fill threads per row
    constexpr int KPT = BK / RT;         // wt floats per fill thread
    constexpr int CPT = KPT * D;         // x floats per fill thread
    constexpr int AFP = TN * DP;
    constexpr int ROWLEN = BN * DP + 4;  // floats, %4==0
    static_assert(ROWLEN % 4 == 0, "rowpad");
    static_assert(AFP % 4 == 0, "afrag");
    constexpr int TILES = M / BK;
    constexpr int NB4 = BK * BW / 4;
    constexpr int AS_BYTES = 2 * BK * ROWLEN * 4;
    static_assert(AS_BYTES + 2 * BK * BW * 4 <= SMEM_BYTES, "smem");

    float (*As)[BK][ROWLEN] = reinterpret_cast<float (*)[BK][ROWLEN]>(smraw);
    float (*Bs)[BK][BW]     = reinterpret_cast<float (*)[BK][BW]>(smraw + AS_BYTES);

    const int tid = threadIdx.x;
    const int twi = tid % THW;
    const int tni = tid / THW;
    const int rf  = tid / RT;
    const int q   = tid % RT;
    const bool rvalid = (n0 + rf) < nrows;
    const float inv_m = 1.0f / (float)M;

    const float* xrow = x  + (size_t)(n0 + rf) * DIM_  + xo + q * CPT;
    const float* wrow = wt + (size_t)(n0 + rf) * WNUM_ + wo + q * KPT;
    const uint32_t bs0 = (uint32_t)__cvta_generic_to_shared(&Bs[0][0][0]);

    ull acc[TN * D][TW / 2];
#pragma unroll
    for (int e = 0; e < TN * D; ++e)
#pragma unroll
        for (int j2 = 0; j2 < TW / 2; ++j2) acc[e][j2] = 0ull;

    alignas(8) float xr[CPT];
    alignas(8) float wr[KPT];

    auto ld_regs = [&](int u0) {
        if (rvalid) {
            const float* xp = xrow + (size_t)u0 * D;
            if constexpr (CPT % 2 == 0) {
#pragma unroll
                for (int v = 0; v < CPT / 2; ++v)
                    reinterpret_cast<float2*>(xr)[v] =
                        reinterpret_cast<const float2*>(xp)[v];
            } else {
#pragma unroll
                for (int v = 0; v < CPT; ++v) xr[v] = xp[v];
            }
            const float* wp = wrow + u0;
            if constexpr (KPT % 2 == 0) {
#pragma unroll
                for (int v = 0; v < KPT / 2; ++v)
                    reinterpret_cast<float2*>(wr)[v] =
                        reinterpret_cast<const float2*>(wp)[v];
            } else {
#pragma unroll
                for (int v = 0; v < KPT; ++v) wr[v] = wp[v];
            }
        } else {
#pragma unroll
            for (int j = 0; j < CPT; ++j) xr[j] = 0.0f;
#pragma unroll
            for (int j = 0; j < KPT; ++j) wr[j] = 0.0f;
        }
    };

    auto ld_bs = [&](int u0, int buf) {
        const float4* src = reinterpret_cast<const float4*>(Wm + (size_t)u0 * M);
        uint32_t dst = bs0 + (uint32_t)buf * (BK * BW * 4);
#pragma unroll
        for (int v = 0; v < (NB4 + NT - 1) / NT; ++v) {
            int idx = tid + v * NT;
            if ((NB4 % NT == 0) || idx < NB4)
                cp_async16(dst + idx * 16, src + idx);
        }
    };

    auto st_as = [&](int buf) {
#pragma unroll
        for (int j = 0; j < CPT; ++j) {
            int kk = q * KPT + j / D;
            int ii = j % D;
            As[buf][kk][rf * DP + ii] = xr[j] * (wr[j / D] * inv_m);
        }
    };

    auto compute = [&](int buf) {
#pragma unroll
        for (int k = 0; k < BK; ++k) {
            alignas(16) float af[AFP];
            const float* ap = &As[buf][k][tni * TN * DP];
#pragma unroll
            for (int v = 0; v < AFP / 4; ++v)
                reinterpret_cast<float4*>(af)[v] =
                    reinterpret_cast<const float4*>(ap)[v];

            ull bf[TW / 2];
            const ull* bp = reinterpret_cast<const ull*>(&Bs[buf][k][0]);
#pragma unroll
            for (int j2 = 0; j2 < TW / 2; ++j2) bf[j2] = bp[twi + j2 * THW];

#pragma unroll
            for (int a = 0; a < TN; ++a)
#pragma unroll
                for (int i = 0; i < D; ++i) {
                    ull a2;
                    asm("mov.b64 %0, {%1, %1};"
                        : "=l"(a2) : "r"(__float_as_uint(af[a * DP + i])));
#pragma unroll
                    for (int j2 = 0; j2 < TW / 2; ++j2)
                        asm("fma.rn.f32x2 %0, %1, %2, %0;"
                            : "+l"(acc[a * D + i][j2]) : "l"(a2), "l"(bf[j2]));
                }
        }
    };

    ld_regs(0);
    ld_bs(0, 0);
    cp_commit();
    st_as(0);
    cp_wait0();
    __syncthreads();

#pragma unroll 1
    for (int t = 0; t < TILES; ++t) {
        const int cur = t & 1;
        if (t + 1 < TILES) {
            ld_regs((t + 1) * BK);
            ld_bs((t + 1) * BK, cur ^ 1);
            cp_commit();
        }
        compute(cur);
        if (t + 1 < TILES) {
            st_as(cur ^ 1);
            cp_wait0();
        }
        __syncthreads();
    }

    // epilogue: w-pair (wlo, wlo+1), wlo = twi*2 + j2*2*THW
#pragma unroll
    for (int a = 0; a < TN; ++a) {
        int gn = n0 + tni * TN + a;
        if (gn >= nrows) continue;
        float* orow = out + (size_t)gn * DIM_ + xo;
#pragma unroll
        for (int j2 = 0; j2 < TW / 2; ++j2) {
            int wlo = twi * 2 + j2 * 2 * THW;
#pragma unroll
            for (int i = 0; i < D; ++i) {
                ull v = acc[a * D + i][j2];
                float lo = __uint_as_float((uint32_t)(v & 0xffffffffull));
                float hi = __uint_as_float((uint32_t)(v >> 32));
                if constexpr (D == 1) {
                    *reinterpret_cast<float2*>(orow + wlo) = make_float2(lo, hi);
                } else {
                    orow[(size_t)wlo * D + i]       = lo;
                    orow[(size_t)(wlo + 1) * D + i] = hi;
                }
            }
        }
    }
}

// chunk pattern of 5 blocks: {b0(32 rows), b1(16), b1(16), b2(32), b3(32)}
__global__ __launch_bounds__(256, 3)
void tp_fused_kernel(const float* __restrict__ x, const float* __restrict__ wt,
                     const float* __restrict__ W0, const float* __restrict__ W1,
                     const float* __restrict__ W2, const float* __restrict__ W3,
                     float* __restrict__ out, int nrows)
{
    __shared__ alignas(16) char smraw[SMEM_BYTES];
    const int bid = blockIdx.x;
    const int r = bid / 5;
    const int t = bid - r * 5;

    if (t == 0) {
        // b0: m=256, d=1 | BN=32, BW=256, BK=16, TN=4, TW=8 (acc 32f)
        run_tp<1, 1, 256, 32, 256, 16, 4, 8>(smraw, x, wt, W0, out,
                                             r * 32, nrows, 0, 0);
    } else if (t <= 2) {
        // b1: m=128, d=3 (DP=4) | BN=16, BW=128, BK=16, TN=2, TW=4 (acc 24f)
        run_tp<3, 4, 128, 16, 128, 16, 2, 4>(smraw, x, wt, W1, out,
                                             (2 * r + (t - 1)) * 16, nrows, 256, 256);
    } else if (t == 3) {
        // b2: m=64, d=5 (DP=6) | BN=32, BW=64, BK=16, TN=2, TW=4 (acc 40f)
        run_tp<5, 6, 64, 32, 64, 16, 2, 4>(smraw, x, wt, W2, out,
                                           r * 32, nrows, 640, 384);
    } else {
        // b3: m=32, d=7 (DP=8) | BN=32, BW=32, BK=16, TN=2, TW=2 (acc 28f)
        run_tp<7, 8, 32, 32, 32, 16, 2, 2>(smraw, x, wt, W3, out,
                                           r * 32, nrows, 960, 448);
    }
}

extern "C" void kernel_launch(void* const* d_in, const int* in_sizes, int n_in,
                              void* d_out, int out_size)
{
    const float* x  = (const float*)d_in[0];
    const float* wtp = (const float*)d_in[1];
    const float* W0 = (const float*)d_in[2];
    const float* W1 = (const float*)d_in[3];
    const float* W2 = (const float*)d_in[4];
    const float* W3 = (const float*)d_in[5];
    float* out = (float*)d_out;

    const int nrows = in_sizes[0] / DIM_;
    const int nchunk = (nrows + 31) / 32;
    tp_fused_kernel<<<nchunk * 5, 256>>>(x, wtp, W0, W1, W2, W3, out, nrows);
}

// round 7
// speedup vs baseline: 1.2280x; 1.0720x over previous
#include <cuda_runtime.h>
#include <cstdint>

// out[n,w,i] = (1/m) * sum_u x[n,u,i] * weight[n,u] * W[u,w]
// Irreps: 256x0e + 128x1o + 64x2e + 32x3o ; DIM=1184, WNUM=480
// Fused single-launch; R7: bigger per-thread tiles to cut smem B/FFMA2
// (proven L1/smem-bound, not occupancy-bound). launch_bounds(256,2) -> 128 regs.

#define DIM_ 1184
#define WNUM_ 480
typedef unsigned long long ull;

__device__ __forceinline__ void cp_async16(uint32_t dst, const void* src) {
    asm volatile("cp.async.cg.shared.global [%0], [%1], 16;" :: "r"(dst), "l"(src));
}
__device__ __forceinline__ void cp_commit() { asm volatile("cp.async.commit_group;"); }
__device__ __forceinline__ void cp_wait0()  { asm volatile("cp.async.wait_group 0;" ::: "memory"); }

#define SMEM_BYTES 41472

template<int D, int DP, int M, int BN, int BW, int BK, int TN, int TW>
__device__ __forceinline__
void run_tp(char* smraw,
            const float* __restrict__ x, const float* __restrict__ wt,
            const float* __restrict__ Wm, float* __restrict__ out,
            int n0, int nrows, int xo, int wo)
{
    constexpr int NT  = 256;
    constexpr int THW = BW / TW;
    constexpr int THN = BN / TN;
    static_assert(THW * THN == NT, "grid");
    constexpr int RT  = NT / BN;         // fill threads per row
    constexpr int KPT = BK / RT;         // wt floats per fill thread
    constexpr int CPT = KPT * D;         // x floats per fill thread
    constexpr int AFP = TN * DP;
    constexpr int ROWLEN = BN * DP + 4;  // floats, %4==0
    static_assert(ROWLEN % 4 == 0, "rowpad");
    static_assert(AFP % 4 == 0, "afrag");
    constexpr int TILES = M / BK;
    constexpr int NB4 = BK * BW / 4;
    constexpr int AS_BYTES = 2 * BK * ROWLEN * 4;
    static_assert(AS_BYTES + 2 * BK * BW * 4 <= SMEM_BYTES, "smem");

    float (*As)[BK][ROWLEN] = reinterpret_cast<float (*)[BK][ROWLEN]>(smraw);
    float (*Bs)[BK][BW]     = reinterpret_cast<float (*)[BK][BW]>(smraw + AS_BYTES);

    const int tid = threadIdx.x;
    const int twi = tid % THW;
    const int tni = tid / THW;
    const int rf  = tid / RT;
    const int q   = tid % RT;
    const bool rvalid = (n0 + rf) < nrows;
    const float inv_m = 1.0f / (float)M;

    const float* xrow = x  + (size_t)(n0 + rf) * DIM_  + xo + q * CPT;
    const float* wrow = wt + (size_t)(n0 + rf) * WNUM_ + wo + q * KPT;
    const uint32_t bs0 = (uint32_t)__cvta_generic_to_shared(&Bs[0][0][0]);

    ull acc[TN * D][TW / 2];
#pragma unroll
    for (int e = 0; e < TN * D; ++e)
#pragma unroll
        for (int j2 = 0; j2 < TW / 2; ++j2) acc[e][j2] = 0ull;

    alignas(16) float xr[CPT];
    alignas(8)  float wr[KPT];

    auto ld_regs = [&](int u0) {
        if (rvalid) {
            const float* xp = xrow + (size_t)u0 * D;
            if constexpr (CPT % 4 == 0) {
#pragma unroll
                for (int v = 0; v < CPT / 4; ++v)
                    reinterpret_cast<float4*>(xr)[v] =
                        reinterpret_cast<const float4*>(xp)[v];
            } else if constexpr (CPT % 2 == 0) {
#pragma unroll
                for (int v = 0; v < CPT / 2; ++v)
                    reinterpret_cast<float2*>(xr)[v] =
                        reinterpret_cast<const float2*>(xp)[v];
            } else {
#pragma unroll
                for (int v = 0; v < CPT; ++v) xr[v] = xp[v];
            }
            const float* wp = wrow + u0;
            if constexpr (KPT % 2 == 0) {
#pragma unroll
                for (int v = 0; v < KPT / 2; ++v)
                    reinterpret_cast<float2*>(wr)[v] =
                        reinterpret_cast<const float2*>(wp)[v];
            } else {
#pragma unroll
                for (int v = 0; v < KPT; ++v) wr[v] = wp[v];
            }
        } else {
#pragma unroll
            for (int j = 0; j < CPT; ++j) xr[j] = 0.0f;
#pragma unroll
            for (int j = 0; j < KPT; ++j) wr[j] = 0.0f;
        }
    };

    auto ld_bs = [&](int u0, int buf) {
        const float4* src = reinterpret_cast<const float4*>(Wm + (size_t)u0 * M);
        uint32_t dst = bs0 + (uint32_t)buf * (BK * BW * 4);
#pragma unroll
        for (int v = 0; v < (NB4 + NT - 1) / NT; ++v) {
            int idx = tid + v * NT;
            if ((NB4 % NT == 0) || idx < NB4)
                cp_async16(dst + idx * 16, src + idx);
        }
    };

    auto st_as = [&](int buf) {
#pragma unroll
        for (int j = 0; j < CPT; ++j) {
            int kk = q * KPT + j / D;
            int ii = j % D;
            As[buf][kk][rf * DP + ii] = xr[j] * (wr[j / D] * inv_m);
        }
    };

    auto compute = [&](int buf) {
#pragma unroll
        for (int k = 0; k < BK; ++k) {
            alignas(16) float af[AFP];
            const float* ap = &As[buf][k][tni * TN * DP];
#pragma unroll
            for (int v = 0; v < AFP / 4; ++v)
                reinterpret_cast<float4*>(af)[v] =
                    reinterpret_cast<const float4*>(ap)[v];

            ull bf[TW / 2];
            const ull* bp = reinterpret_cast<const ull*>(&Bs[buf][k][0]);
#pragma unroll
            for (int j2 = 0; j2 < TW / 2; ++j2) bf[j2] = bp[twi + j2 * THW];

#pragma unroll
            for (int a = 0; a < TN; ++a)
#pragma unroll
                for (int i = 0; i < D; ++i) {
                    ull a2;
                    asm("mov.b64 %0, {%1, %1};"
                        : "=l"(a2) : "r"(__float_as_uint(af[a * DP + i])));
#pragma unroll
                    for (int j2 = 0; j2 < TW / 2; ++j2)
                        asm("fma.rn.f32x2 %0, %1, %2, %0;"
                            : "+l"(acc[a * D + i][j2]) : "l"(a2), "l"(bf[j2]));
                }
        }
    };

    ld_regs(0);
    ld_bs(0, 0);
    cp_commit();
    st_as(0);
    cp_wait0();
    __syncthreads();

#pragma unroll 1
    for (int t = 0; t < TILES; ++t) {
        const int cur = t & 1;
        if (t + 1 < TILES) {
            ld_regs((t + 1) * BK);
            ld_bs((t + 1) * BK, cur ^ 1);
            cp_commit();
        }
        compute(cur);
        if (t + 1 < TILES) {
            st_as(cur ^ 1);
            cp_wait0();
        }
        __syncthreads();
    }

    // epilogue: w-pair (wlo, wlo+1), wlo = twi*2 + j2*2*THW
#pragma unroll
    for (int a = 0; a < TN; ++a) {
        int gn = n0 + tni * TN + a;
        if (gn >= nrows) continue;
        float* orow = out + (size_t)gn * DIM_ + xo;
#pragma unroll
        for (int j2 = 0; j2 < TW / 2; ++j2) {
            int wlo = twi * 2 + j2 * 2 * THW;
#pragma unroll
            for (int i = 0; i < D; ++i) {
                ull v = acc[a * D + i][j2];
                float lo = __uint_as_float((uint32_t)(v & 0xffffffffull));
                float hi = __uint_as_float((uint32_t)(v >> 32));
                if constexpr (D == 1) {
                    *reinterpret_cast<float2*>(orow + wlo) = make_float2(lo, hi);
                } else {
                    orow[(size_t)wlo * D + i]       = lo;
                    orow[(size_t)(wlo + 1) * D + i] = hi;
                }
            }
        }
    }
}

// chunk pattern of 6 blocks per 64 rows: {b0(64), b1(32)x2, b2(32)x2, b3(64)}
__global__ __launch_bounds__(256, 2)
void tp_fused_kernel(const float* __restrict__ x, const float* __restrict__ wt,
                     const float* __restrict__ W0, const float* __restrict__ W1,
                     const float* __restrict__ W2, const float* __restrict__ W3,
                     float* __restrict__ out, int nrows)
{
    __shared__ alignas(16) char smraw[SMEM_BYTES];
    const int bid = blockIdx.x;
    const int r = bid / 6;
    const int t = bid - r * 6;

    if (t == 0) {
        // b0: m=256, d=1 | BN=64, BW=256, BK=16, TN=8, TW=8 (2.0 B/FFMA2)
        run_tp<1, 1, 256, 64, 256, 16, 8, 8>(smraw, x, wt, W0, out,
                                             r * 64, nrows, 0, 0);
    } else if (t <= 2) {
        // b1: m=128, d=3 (DP=4) | BN=32, BW=128, BK=16, TN=2, TW=8 (2.67)
        run_tp<3, 4, 128, 32, 128, 16, 2, 8>(smraw, x, wt, W1, out,
                                             (2 * r + (t - 1)) * 32, nrows, 256, 256);
    } else if (t <= 4) {
        // b2: m=64, d=5 (DP=6) | BN=32, BW=64, BK=16, TN=2, TW=4 (3.2)
        run_tp<5, 6, 64, 32, 64, 16, 2, 4>(smraw, x, wt, W2, out,
                                           (2 * r + (t - 3)) * 32, nrows, 640, 384);
    } else {
        // b3: m=32, d=7 (DP=8) | BN=64, BW=32, BK=8, TN=2, TW=4 (2.9)
        run_tp<7, 8, 32, 64, 32, 8, 2, 4>(smraw, x, wt, W3, out,
                                          r * 64, nrows, 960, 448);
    }
}

extern "C" void kernel_launch(void* const* d_in, const int* in_sizes, int n_in,
                              void* d_out, int out_size)
{
    const float* x  = (const float*)d_in[0];
    const float* wtp = (const float*)d_in[1];
    const float* W0 = (const float*)d_in[2];
    const float* W1 = (const float*)d_in[3];
    const float* W2 = (const float*)d_in[4];
    const float* W3 = (const float*)d_in[5];
    float* out = (float*)d_out;

    const int nrows = in_sizes[0] / DIM_;
    const int nchunk = (nrows + 63) / 64;
    tp_fused_kernel<<<nchunk * 6, 256>>>(x, wtp, W0, W1, W2, W3, out, nrows);
}